// round 7
// baseline (speedup 1.0000x reference)
#include <cuda_runtime.h>
#include <cuda_bf16.h>
#include <math.h>
#include <stdint.h>

// Problem constants
#define B_SZ 8
#define L_SZ 1024
#define DM 1024
#define NH 16
#define NG 4
#define HD 64
#define QKV_E 1536
#define MROWS (B_SZ * L_SZ)   // 8192

// ---------------- scratch (device globals; no allocation allowed) ----------
__device__ float g_qkv[MROWS * QKV_E];
__device__ __nv_bfloat16 g_xh[MROWS * DM];
__device__ __nv_bfloat16 g_xl[MROWS * DM];
__device__ __nv_bfloat16 g_wqh[QKV_E * DM];
__device__ __nv_bfloat16 g_wql[QKV_E * DM];
__device__ __nv_bfloat16 g_woh[DM * DM];
__device__ __nv_bfloat16 g_wol[DM * DM];
__device__ __nv_bfloat16 g_ah[MROWS * DM];
__device__ __nv_bfloat16 g_al[MROWS * DM];
__device__ __nv_bfloat16 g_qh[B_SZ * NH * L_SZ * HD];
__device__ __nv_bfloat16 g_ql[B_SZ * NH * L_SZ * HD];
__device__ __nv_bfloat16 g_kh[B_SZ * NG * L_SZ * HD];
__device__ __nv_bfloat16 g_kl[B_SZ * NG * L_SZ * HD];
__device__ __nv_bfloat16 g_vth[B_SZ * NG * HD * L_SZ];  // [b,g,d,l]
__device__ __nv_bfloat16 g_vtl[B_SZ * NG * HD * L_SZ];

// ============================================================================
// helpers
// ============================================================================
__device__ __forceinline__ uint32_t smem_u32(const void* p) {
    uint32_t a;
    asm("{ .reg .u64 t; cvta.to.shared.u64 t, %1; cvt.u32.u64 %0, t; }"
        : "=r"(a) : "l"(p));
    return a;
}

__device__ __forceinline__ void ldsm4(uint32_t* r, uint32_t addr) {
    asm volatile("ldmatrix.sync.aligned.m8n8.x4.shared.b16 {%0,%1,%2,%3}, [%4];"
        : "=r"(r[0]), "=r"(r[1]), "=r"(r[2]), "=r"(r[3]) : "r"(addr));
}

__device__ __forceinline__ void mma_bf16(float* d, const uint32_t* a,
                                         const uint32_t* b) {
    asm volatile(
        "mma.sync.aligned.m16n8k16.row.col.f32.bf16.bf16.f32 "
        "{%0,%1,%2,%3}, {%4,%5,%6,%7}, {%8,%9}, {%0,%1,%2,%3};"
        : "+f"(d[0]), "+f"(d[1]), "+f"(d[2]), "+f"(d[3])
        : "r"(a[0]), "r"(a[1]), "r"(a[2]), "r"(a[3]), "r"(b[0]), "r"(b[1]));
}

__device__ __forceinline__ void split2(float a, float b, uint32_t& hi, uint32_t& lo) {
    __nv_bfloat162 h = __float22bfloat162_rn(make_float2(a, b));
    float2 hf = __bfloat1622float2(h);
    __nv_bfloat162 l = __float22bfloat162_rn(make_float2(a - hf.x, b - hf.y));
    hi = *(uint32_t*)&h;
    lo = *(uint32_t*)&l;
}

__device__ __forceinline__ void split1(float v, __nv_bfloat16& h, __nv_bfloat16& l) {
    h = __float2bfloat16(v);
    l = __float2bfloat16(v - __bfloat162float(h));
}

__device__ __forceinline__ void split8(const float4 v0, const float4 v1,
                                       uint4& hi, uint4& lo) {
    const float f[8] = {v0.x, v0.y, v0.z, v0.w, v1.x, v1.y, v1.z, v1.w};
    uint32_t h[4], l[4];
#pragma unroll
    for (int i = 0; i < 4; i++) {
        __nv_bfloat162 hh = __float22bfloat162_rn(make_float2(f[2*i], f[2*i+1]));
        float2 hf = __bfloat1622float2(hh);
        __nv_bfloat162 ll = __float22bfloat162_rn(
            make_float2(f[2*i] - hf.x, f[2*i+1] - hf.y));
        h[i] = *(uint32_t*)&hh;
        l[i] = *(uint32_t*)&ll;
    }
    hi = make_uint4(h[0], h[1], h[2], h[3]);
    lo = make_uint4(l[0], l[1], l[2], l[3]);
}

#define CP16(smem_addr, gptr) \
    asm volatile("cp.async.cg.shared.global [%0], [%1], 16;" :: "r"(smem_addr), "l"(gptr))
#define CP_COMMIT() asm volatile("cp.async.commit_group;" ::: "memory")
#define CP_WAIT1()  asm volatile("cp.async.wait_group 1;" ::: "memory")
#define CP_WAIT2()  asm volatile("cp.async.wait_group 2;" ::: "memory")

// ============================================================================
// Kernel 0: fp32 -> bf16 hi/lo split
// ============================================================================
__global__ void __launch_bounds__(256) convert_kernel(
    const float* __restrict__ src,
    __nv_bfloat16* __restrict__ h, __nv_bfloat16* __restrict__ l, int n8)
{
    int i = blockIdx.x * blockDim.x + threadIdx.x;
    if (i >= n8) return;
    float4 v0 = ((const float4*)src)[2 * i];
    float4 v1 = ((const float4*)src)[2 * i + 1];
    uint4 hi, lo;
    split8(v0, v1, hi, lo);
    ((uint4*)h)[i] = hi;
    ((uint4*)l)[i] = lo;
}

// ============================================================================
// Kernel 1: C[M,N] = A[M,K] @ B[N,K]^T, pre-split bf16 hi/lo operands.
// Pass-major MMA ordering: accumulator reuse distance = 16 MMAs.
// ============================================================================
#define PSTAGE 32768
#define PGEMM_SMEM (3 * PSTAGE)   // 96KB

__global__ void __launch_bounds__(256, 2) gemm_pre_kernel(
    const __nv_bfloat16* __restrict__ Ah, const __nv_bfloat16* __restrict__ Al,
    const __nv_bfloat16* __restrict__ Bh, const __nv_bfloat16* __restrict__ Bl,
    float* __restrict__ C, int N, int K)
{
    extern __shared__ char smem[];
    const uint32_t sb = smem_u32(smem);
    const int tid = threadIdx.x;
    const int wid = tid >> 5;
    const int lane = tid & 31;
    const int m0 = blockIdx.y * 128;
    const int n0 = blockIdx.x * 128;
    const int NC = K >> 5;

    const int warp_m = wid & 3;
    const int warp_n = wid >> 2;

    const int lrow = tid >> 1;
    const int swz_l = (lrow >> 1) & 3;
    const uint32_t so0 = lrow * 64 + ((((tid & 1) * 2 + 0) ^ swz_l) << 4);
    const uint32_t so1 = lrow * 64 + ((((tid & 1) * 2 + 1) ^ swz_l) << 4);
    const size_t roA0 = (size_t)(m0 + lrow) * K + (tid & 1) * 16;
    const size_t roB0 = (size_t)(n0 + lrow) * K + (tid & 1) * 16;

    auto issue = [&](int c, int st) {
        const uint32_t base = sb + st * PSTAGE;
        const size_t ra = roA0 + c * 32;
        const size_t rb = roB0 + c * 32;
        CP16(base + so0,         Ah + ra);
        CP16(base + so1,         Ah + ra + 8);
        CP16(base + 8192 + so0,  Al + ra);
        CP16(base + 8192 + so1,  Al + ra + 8);
        CP16(base + 16384 + so0, Bh + rb);
        CP16(base + 16384 + so1, Bh + rb + 8);
        CP16(base + 24576 + so0, Bl + rb);
        CP16(base + 24576 + so1, Bl + rb + 8);
    };

    uint32_t aoff[2][2];
#pragma unroll
    for (int tm = 0; tm < 2; tm++) {
        int r = warp_m * 32 + tm * 16 + (lane & 15);
        int sw = (r >> 1) & 3;
#pragma unroll
        for (int ks = 0; ks < 2; ks++) {
            int ch = ks * 2 + (lane >> 4);
            aoff[tm][ks] = r * 64 + ((ch ^ sw) << 4);
        }
    }
    uint32_t boff[4][2];
#pragma unroll
    for (int bp = 0; bp < 4; bp++) {
        int r = warp_n * 64 + bp * 16 + ((lane >> 4) << 3) + (lane & 7);
        int sw = (r >> 1) & 3;
#pragma unroll
        for (int ks = 0; ks < 2; ks++) {
            int ch = ks * 2 + ((lane >> 3) & 1);
            boff[bp][ks] = r * 64 + ((ch ^ sw) << 4);
        }
    }

    float acc[2][8][4];
#pragma unroll
    for (int i = 0; i < 2; i++)
#pragma unroll
        for (int j = 0; j < 8; j++)
#pragma unroll
            for (int q = 0; q < 4; q++) acc[i][j][q] = 0.f;

    issue(0, 0); CP_COMMIT();
    issue(1, 1); CP_COMMIT();
    issue(2, 2); CP_COMMIT();

    int st = 0;
#pragma unroll 1
    for (int bk = 0; bk < NC; bk++) {
        CP_WAIT2();
        __syncthreads();

        const uint32_t ah = sb + st * PSTAGE;
        const uint32_t al = ah + 8192;
        const uint32_t wh = ah + 16384;
        const uint32_t wl = ah + 24576;
#pragma unroll
        for (int ks = 0; ks < 2; ks++) {
            uint32_t fa[2][4], fal[2][4];
#pragma unroll
            for (int tm = 0; tm < 2; tm++) {
                ldsm4(fa[tm], ah + aoff[tm][ks]);
                ldsm4(fal[tm], al + aoff[tm][ks]);
            }
            uint32_t fb[8][2], fbl[8][2];
#pragma unroll
            for (int bp = 0; bp < 4; bp++) {
                uint32_t t[4];
                ldsm4(t, wh + boff[bp][ks]);
                fb[2*bp][0] = t[0]; fb[2*bp][1] = t[1];
                fb[2*bp+1][0] = t[2]; fb[2*bp+1][1] = t[3];
                ldsm4(t, wl + boff[bp][ks]);
                fbl[2*bp][0] = t[0]; fbl[2*bp][1] = t[1];
                fbl[2*bp+1][0] = t[2]; fbl[2*bp+1][1] = t[3];
            }
            // pass-major: each acc tile touched once per pass (reuse dist 16)
#pragma unroll
            for (int tm = 0; tm < 2; tm++)
#pragma unroll
                for (int tn = 0; tn < 8; tn++)
                    mma_bf16(acc[tm][tn], fa[tm], fb[tn]);    // hi*hi
#pragma unroll
            for (int tm = 0; tm < 2; tm++)
#pragma unroll
                for (int tn = 0; tn < 8; tn++)
                    mma_bf16(acc[tm][tn], fal[tm], fb[tn]);   // lo*hi
#pragma unroll
            for (int tm = 0; tm < 2; tm++)
#pragma unroll
                for (int tn = 0; tn < 8; tn++)
                    mma_bf16(acc[tm][tn], fa[tm], fbl[tn]);   // hi*lo
        }

        __syncthreads();
        if (bk + 3 < NC) issue(bk + 3, st);
        CP_COMMIT();
        st = (st == 2) ? 0 : st + 1;
    }

    const int er = lane >> 2;
    const int ec = (lane & 3) * 2;
#pragma unroll
    for (int tm = 0; tm < 2; tm++) {
        const int rbase = m0 + warp_m * 32 + tm * 16 + er;
#pragma unroll
        for (int tn = 0; tn < 8; tn++) {
            const int cbase = n0 + warp_n * 64 + tn * 8 + ec;
            float* p0 = C + (size_t)rbase * N + cbase;
            float* p1 = C + (size_t)(rbase + 8) * N + cbase;
            *(float2*)p0 = make_float2(acc[tm][tn][0], acc[tm][tn][1]);
            *(float2*)p1 = make_float2(acc[tm][tn][2], acc[tm][tn][3]);
        }
    }
}

// ============================================================================
// Kernel 2: qk-norm + RoPE2D + transpose -> bf16 hi/lo outputs.
// ============================================================================
__global__ void __launch_bounds__(256) norm_rope_kernel(
    const float* __restrict__ qkv,
    __nv_bfloat16* __restrict__ qh, __nv_bfloat16* __restrict__ ql,
    __nv_bfloat16* __restrict__ kh, __nv_bfloat16* __restrict__ kl,
    __nv_bfloat16* __restrict__ vth, __nv_bfloat16* __restrict__ vtl)
{
    const int gwarp = (blockIdx.x * blockDim.x + threadIdx.x) >> 5;
    const int lane = threadIdx.x & 31;
    const int NVEC = MROWS * 24;
    if (gwarp >= NVEC) return;

    const int bl = gwarp / 24;
    const int slot = gwarp % 24;
    const int b = bl >> 10;
    const int l = bl & 1023;

    const float2 xv = *(const float2*)(qkv + (size_t)bl * QKV_E + slot * 64 + 2 * lane);
    float x1 = xv.x, x2 = xv.y;

    if (slot < 20) {
        float ss = x1 * x1 + x2 * x2;
#pragma unroll
        for (int o = 16; o > 0; o >>= 1)
            ss += __shfl_xor_sync(0xffffffffu, ss, o);
        float inv = 1.f / (sqrtf(ss) + 1e-10f);
        if (slot < 16) inv *= 0.18033688011112042f;  // 0.125 * log2(e)
        x1 *= inv; x2 *= inv;

        float psum = (float)((l >> 5) + (l & 31));
        float invfreq = exp2f(-0.41524101186098287f * (float)lane);
        float fr = psum * invfreq;
        float s, c;
        sincosf(fr, &s, &c);
        float olo = x1 * c - x2 * s;
        float ohi = x1 * s + x2 * c;

        __nv_bfloat16 *dh, *dl;
        if (slot < 16) {
            size_t base = (((size_t)b * NH + slot) * L_SZ + l) * HD;
            dh = qh + base; dl = ql + base;
        } else {
            size_t base = (((size_t)b * NG + (slot - 16)) * L_SZ + l) * HD;
            dh = kh + base; dl = kl + base;
        }
        __nv_bfloat16 h, lo;
        split1(olo, h, lo); dh[lane] = h; dl[lane] = lo;
        split1(ohi, h, lo); dh[lane + 32] = h; dl[lane + 32] = lo;
    } else {
        const int sv = slot - 20;
        const size_t base = ((size_t)b * NG + sv) * HD * L_SZ;
        __nv_bfloat16 h, lo;
        split1(x1, h, lo);
        vth[base + (size_t)(2 * lane) * L_SZ + l] = h;
        vtl[base + (size_t)(2 * lane) * L_SZ + l] = lo;
        split1(x2, h, lo);
        vth[base + (size_t)(2 * lane + 1) * L_SZ + l] = h;
        vtl[base + (size_t)(2 * lane + 1) * L_SZ + l] = lo;
    }
}

// ============================================================================
// Kernel 3: tensor-core flash attention, pass-major MMA ordering.
// ============================================================================
#define A_OFF_QH 0
#define A_OFF_QL 16384
#define A_OFF_KV 32768
#define A_STAGE  32768
#define ATTN_SMEM (A_OFF_KV + 2 * A_STAGE)   // 96KB

__global__ void __launch_bounds__(256, 1) attn_mma_kernel(
    const __nv_bfloat16* __restrict__ qh, const __nv_bfloat16* __restrict__ ql,
    const __nv_bfloat16* __restrict__ kh, const __nv_bfloat16* __restrict__ kl,
    const __nv_bfloat16* __restrict__ vth, const __nv_bfloat16* __restrict__ vtl,
    __nv_bfloat16* __restrict__ Oh, __nv_bfloat16* __restrict__ Ol)
{
    extern __shared__ char smem[];
    const uint32_t sb = smem_u32(smem);
    const int tid = threadIdx.x;
    const int wid = tid >> 5;
    const int lane = tid & 31;

    const int qt = blockIdx.x;
    const int h = blockIdx.y;
    const int b = blockIdx.z;
    const int g = h >> 2;

    const __nv_bfloat16* Qh_g = qh + ((((size_t)b * NH + h) * L_SZ) + qt * 128) * HD;
    const __nv_bfloat16* Ql_g = ql + ((((size_t)b * NH + h) * L_SZ) + qt * 128) * HD;
    const __nv_bfloat16* Kh_g = kh + (((size_t)b * NG + g) * L_SZ) * HD;
    const __nv_bfloat16* Kl_g = kl + (((size_t)b * NG + g) * L_SZ) * HD;
    const __nv_bfloat16* Vth_g = vth + ((size_t)b * NG + g) * HD * L_SZ;
    const __nv_bfloat16* Vtl_g = vtl + ((size_t)b * NG + g) * HD * L_SZ;

#pragma unroll
    for (int i = 0; i < 4; i++) {
        int idx = tid * 4 + i;
        int row = idx >> 3, ch = idx & 7;
        uint32_t sw = (uint32_t)(row * 128 + ((ch ^ (row & 7)) << 4));
        CP16(sb + A_OFF_QH + sw, Qh_g + row * 64 + ch * 8);
        CP16(sb + A_OFF_QL + sw, Ql_g + row * 64 + ch * 8);
    }

    auto issue_chunk = [&](int c, int st) {
        const uint32_t base = sb + A_OFF_KV + st * A_STAGE;
#pragma unroll
        for (int i = 0; i < 2; i++) {
            int idx = tid * 2 + i;
            int row = idx >> 3, ch = idx & 7;
            uint32_t sw = (uint32_t)(row * 128 + ((ch ^ (row & 7)) << 4));
            CP16(base + sw,         Kh_g + (size_t)(c * 64 + row) * 64 + ch * 8);
            CP16(base + 8192 + sw,  Kl_g + (size_t)(c * 64 + row) * 64 + ch * 8);
            CP16(base + 16384 + sw, Vth_g + (size_t)row * L_SZ + c * 64 + ch * 8);
            CP16(base + 24576 + sw, Vtl_g + (size_t)row * L_SZ + c * 64 + ch * 8);
        }
    };

    issue_chunk(0, 0);
    CP_COMMIT();
    issue_chunk(1, 1);
    CP_COMMIT();

    uint32_t qoff[4];
#pragma unroll
    for (int ks = 0; ks < 4; ks++) {
        int r = wid * 16 + (lane & 15);
        int ch = ks * 2 + (lane >> 4);
        qoff[ks] = (uint32_t)(r * 128 + ((ch ^ (r & 7)) << 4));
    }
    uint32_t lbo[4][4];
#pragma unroll
    for (int np = 0; np < 4; np++) {
        int r = np * 16 + ((lane >> 4) << 3) + (lane & 7);
#pragma unroll
        for (int ks = 0; ks < 4; ks++) {
            int ch = ks * 2 + ((lane >> 3) & 1);
            lbo[np][ks] = (uint32_t)(r * 128 + ((ch ^ (r & 7)) << 4));
        }
    }

    uint32_t qfh[4][4], qfl[4][4];
    float oacc[8][4];
#pragma unroll
    for (int t = 0; t < 8; t++)
#pragma unroll
        for (int q = 0; q < 4; q++) oacc[t][q] = 0.f;
    float mrow[2] = {-INFINITY, -INFINITY};
    float lrow[2] = {0.f, 0.f};

#pragma unroll 1
    for (int c = 0; c < 16; c++) {
        const int st = c & 1;
        CP_WAIT1();
        __syncthreads();

        if (c == 0) {
#pragma unroll
            for (int ks = 0; ks < 4; ks++) {
                ldsm4(qfh[ks], sb + A_OFF_QH + qoff[ks]);
                ldsm4(qfl[ks], sb + A_OFF_QL + qoff[ks]);
            }
        }

        const uint32_t kb = sb + A_OFF_KV + st * A_STAGE;
        const uint32_t vb = kb + 16384;

        // ---- S = Q K^T, pass-major within each k-step ----
        float sacc[8][4];
#pragma unroll
        for (int t = 0; t < 8; t++)
#pragma unroll
            for (int q = 0; q < 4; q++) sacc[t][q] = 0.f;
#pragma unroll
        for (int ks = 0; ks < 4; ks++) {
            uint32_t kth[4][4], ktl[4][4];
#pragma unroll
            for (int np = 0; np < 4; np++) {
                ldsm4(kth[np], kb + lbo[np][ks]);
                ldsm4(ktl[np], kb + 8192 + lbo[np][ks]);
            }
#pragma unroll
            for (int np = 0; np < 4; np++) {
                mma_bf16(sacc[2*np],   qfh[ks], kth[np]);
                mma_bf16(sacc[2*np+1], qfh[ks], kth[np] + 2);
            }
#pragma unroll
            for (int np = 0; np < 4; np++) {
                mma_bf16(sacc[2*np],   qfl[ks], kth[np]);
                mma_bf16(sacc[2*np+1], qfl[ks], kth[np] + 2);
            }
#pragma unroll
            for (int np = 0; np < 4; np++) {
                mma_bf16(sacc[2*np],   qfh[ks], ktl[np]);
                mma_bf16(sacc[2*np+1], qfh[ks], ktl[np] + 2);
            }
        }

        // ---- online softmax ----
#pragma unroll
        for (int r = 0; r < 2; r++) {
            float mx = mrow[r];
#pragma unroll
            for (int t = 0; t < 8; t++)
                mx = fmaxf(mx, fmaxf(sacc[t][2*r], sacc[t][2*r+1]));
            mx = fmaxf(mx, __shfl_xor_sync(0xffffffffu, mx, 1));
            mx = fmaxf(mx, __shfl_xor_sync(0xffffffffu, mx, 2));
            const float sc = exp2f(mrow[r] - mx);
            mrow[r] = mx;
            float sum = 0.f;
#pragma unroll
            for (int t = 0; t < 8; t++) {
                float p0 = exp2f(sacc[t][2*r]   - mx);
                float p1 = exp2f(sacc[t][2*r+1] - mx);
                sacc[t][2*r] = p0; sacc[t][2*r+1] = p1;
                sum += p0 + p1;
            }
            sum += __shfl_xor_sync(0xffffffffu, sum, 1);
            sum += __shfl_xor_sync(0xffffffffu, sum, 2);
            lrow[r] = lrow[r] * sc + sum;
#pragma unroll
            for (int t = 0; t < 8; t++) {
                oacc[t][2*r] *= sc; oacc[t][2*r+1] *= sc;
            }
        }

        // ---- O += P V, pass-major within each j-step ----
#pragma unroll
        for (int j = 0; j < 4; j++) {
            uint32_t pah[4], pal[4];
            split2(sacc[2*j][0],   sacc[2*j][1],   pah[0], pal[0]);
            split2(sacc[2*j][2],   sacc[2*j][3],   pah[1], pal[1]);
            split2(sacc[2*j+1][0], sacc[2*j+1][1], pah[2], pal[2]);
            split2(sacc[2*j+1][2], sacc[2*j+1][3], pah[3], pal[3]);
            uint32_t vfh[4][4], vfl[4][4];
#pragma unroll
            for (int dp = 0; dp < 4; dp++) {
                ldsm4(vfh[dp], vb + lbo[dp][j]);
                ldsm4(vfl[dp], vb + 8192 + lbo[dp][j]);
            }
#pragma unroll
            for (int dp = 0; dp < 4; dp++) {
                mma_bf16(oacc[2*dp],   pah, vfh[dp]);
                mma_bf16(oacc[2*dp+1], pah, vfh[dp] + 2);
            }
#pragma unroll
            for (int dp = 0; dp < 4; dp++) {
                mma_bf16(oacc[2*dp],   pal, vfh[dp]);
                mma_bf16(oacc[2*dp+1], pal, vfh[dp] + 2);
            }
#pragma unroll
            for (int dp = 0; dp < 4; dp++) {
                mma_bf16(oacc[2*dp],   pah, vfl[dp]);
                mma_bf16(oacc[2*dp+1], pah, vfl[dp] + 2);
            }
        }

        __syncthreads();
        if (c + 2 < 16) issue_chunk(c + 2, st);
        CP_COMMIT();
    }

    // ---- normalize + split to bf16 hi/lo, write [b, l, h*64+d] ----
    const float inv0 = 1.f / lrow[0];
    const float inv1 = 1.f / lrow[1];
    const int q0 = qt * 128 + wid * 16 + (lane >> 2);
#pragma unroll
    for (int t = 0; t < 8; t++) {
        const int col = h * 64 + t * 8 + (lane & 3) * 2;
        const size_t o0 = ((size_t)(b * L_SZ + q0)) * DM + col;
        const size_t o1 = ((size_t)(b * L_SZ + q0 + 8)) * DM + col;
        uint32_t hi, lo;
        split2(oacc[t][0] * inv0, oacc[t][1] * inv0, hi, lo);
        *(uint32_t*)(Oh + o0) = hi;
        *(uint32_t*)(Ol + o0) = lo;
        split2(oacc[t][2] * inv1, oacc[t][3] * inv1, hi, lo);
        *(uint32_t*)(Oh + o1) = hi;
        *(uint32_t*)(Ol + o1) = lo;
    }
}

// ============================================================================
// launch
// ============================================================================
extern "C" void kernel_launch(void* const* d_in, const int* in_sizes, int n_in,
                              void* d_out, int out_size)
{
    const float* x     = (const float*)d_in[0];
    const float* w_qkv = (const float*)d_in[1];
    const float* w_o   = (const float*)d_in[2];
    float* out = (float*)d_out;

    float* qkv_p;
    __nv_bfloat16 *xh_p, *xl_p, *wqh_p, *wql_p, *woh_p, *wol_p, *ah_p, *al_p;
    __nv_bfloat16 *qh_p, *ql_p, *kh_p, *kl_p, *vth_p, *vtl_p;
    cudaGetSymbolAddress((void**)&qkv_p, g_qkv);
    cudaGetSymbolAddress((void**)&xh_p,  g_xh);
    cudaGetSymbolAddress((void**)&xl_p,  g_xl);
    cudaGetSymbolAddress((void**)&wqh_p, g_wqh);
    cudaGetSymbolAddress((void**)&wql_p, g_wql);
    cudaGetSymbolAddress((void**)&woh_p, g_woh);
    cudaGetSymbolAddress((void**)&wol_p, g_wol);
    cudaGetSymbolAddress((void**)&ah_p,  g_ah);
    cudaGetSymbolAddress((void**)&al_p,  g_al);
    cudaGetSymbolAddress((void**)&qh_p,  g_qh);
    cudaGetSymbolAddress((void**)&ql_p,  g_ql);
    cudaGetSymbolAddress((void**)&kh_p,  g_kh);
    cudaGetSymbolAddress((void**)&kl_p,  g_kl);
    cudaGetSymbolAddress((void**)&vth_p, g_vth);
    cudaGetSymbolAddress((void**)&vtl_p, g_vtl);

    cudaFuncSetAttribute(gemm_pre_kernel,
                         cudaFuncAttributeMaxDynamicSharedMemorySize, PGEMM_SMEM);
    cudaFuncSetAttribute(attn_mma_kernel,
                         cudaFuncAttributeMaxDynamicSharedMemorySize, ATTN_SMEM);

    convert_kernel<<<(MROWS * DM / 8 + 255) / 256, 256>>>(x, xh_p, xl_p, MROWS * DM / 8);
    convert_kernel<<<(QKV_E * DM / 8 + 255) / 256, 256>>>(w_qkv, wqh_p, wql_p, QKV_E * DM / 8);
    convert_kernel<<<(DM * DM / 8 + 255) / 256, 256>>>(w_o, woh_p, wol_p, DM * DM / 8);

    {
        dim3 grid(QKV_E / 128, MROWS / 128);
        gemm_pre_kernel<<<grid, 256, PGEMM_SMEM>>>(xh_p, xl_p, wqh_p, wql_p,
                                                   qkv_p, QKV_E, DM);
    }
    {
        int nvec = MROWS * 24;
        int blocks = (nvec + 7) / 8;
        norm_rope_kernel<<<blocks, 256>>>(qkv_p, qh_p, ql_p, kh_p, kl_p, vth_p, vtl_p);
    }
    {
        dim3 grid(L_SZ / 128, NH, B_SZ);
        attn_mma_kernel<<<grid, 256, ATTN_SMEM>>>(qh_p, ql_p, kh_p, kl_p,
                                                  vth_p, vtl_p, ah_p, al_p);
    }
    {
        dim3 grid(DM / 128, MROWS / 128);
        gemm_pre_kernel<<<grid, 256, PGEMM_SMEM>>>(ah_p, al_p, woh_p, wol_p,
                                                   out, DM, DM);
    }
}

// round 8
// speedup vs baseline: 1.4991x; 1.4991x over previous
#include <cuda_runtime.h>
#include <cuda_fp16.h>
#include <math.h>
#include <stdint.h>

// Problem constants
#define B_SZ 8
#define L_SZ 1024
#define DM 1024
#define NH 16
#define NG 4
#define HD 64
#define QKV_E 1536
#define MROWS (B_SZ * L_SZ)   // 8192

// ---------------- scratch (device globals; no allocation allowed) ----------
__device__ float g_qkv[MROWS * QKV_E];
__device__ __half g_xh[MROWS * DM];
__device__ __half g_xl[MROWS * DM];
__device__ __half g_wqh[QKV_E * DM];
__device__ __half g_woh[DM * DM];
__device__ __half g_ah[MROWS * DM];      // attention output hi
__device__ __half g_al[MROWS * DM];      // attention output lo
__device__ __half g_qh[B_SZ * NH * L_SZ * HD];
__device__ __half g_kh[B_SZ * NG * L_SZ * HD];
__device__ __half g_vth[B_SZ * NG * HD * L_SZ];  // [b,g,d,l]
__device__ __half g_vtl[B_SZ * NG * HD * L_SZ];

// ============================================================================
// helpers
// ============================================================================
__device__ __forceinline__ uint32_t smem_u32(const void* p) {
    uint32_t a;
    asm("{ .reg .u64 t; cvta.to.shared.u64 t, %1; cvt.u32.u64 %0, t; }"
        : "=r"(a) : "l"(p));
    return a;
}

__device__ __forceinline__ void ldsm4(uint32_t* r, uint32_t addr) {
    asm volatile("ldmatrix.sync.aligned.m8n8.x4.shared.b16 {%0,%1,%2,%3}, [%4];"
        : "=r"(r[0]), "=r"(r[1]), "=r"(r[2]), "=r"(r[3]) : "r"(addr));
}

__device__ __forceinline__ void mma_f16(float* d, const uint32_t* a,
                                        const uint32_t* b) {
    asm volatile(
        "mma.sync.aligned.m16n8k16.row.col.f32.f16.f16.f32 "
        "{%0,%1,%2,%3}, {%4,%5,%6,%7}, {%8,%9}, {%0,%1,%2,%3};"
        : "+f"(d[0]), "+f"(d[1]), "+f"(d[2]), "+f"(d[3])
        : "r"(a[0]), "r"(a[1]), "r"(a[2]), "r"(a[3]), "r"(b[0]), "r"(b[1]));
}

__device__ __forceinline__ uint32_t pack2h(float a, float b) {
    __half2 h = __floats2half2_rn(a, b);
    return *(uint32_t*)&h;
}

__device__ __forceinline__ void split2h(float a, float b, uint32_t& hi, uint32_t& lo) {
    __half2 h = __floats2half2_rn(a, b);
    float2 hf = __half22float2(h);
    __half2 l = __floats2half2_rn(a - hf.x, b - hf.y);
    hi = *(uint32_t*)&h;
    lo = *(uint32_t*)&l;
}

__device__ __forceinline__ void split1h(float v, __half& h, __half& l) {
    h = __float2half_rn(v);
    l = __float2half_rn(v - __half2float(h));
}

#define CP16(smem_addr, gptr) \
    asm volatile("cp.async.cg.shared.global [%0], [%1], 16;" :: "r"(smem_addr), "l"(gptr))
#define CP_COMMIT() asm volatile("cp.async.commit_group;" ::: "memory")
#define CP_WAIT1()  asm volatile("cp.async.wait_group 1;" ::: "memory")
#define CP_WAIT2()  asm volatile("cp.async.wait_group 2;" ::: "memory")

// ============================================================================
// Kernel 0a: fp32 -> fp16 hi/lo split (activations)
// ============================================================================
__global__ void __launch_bounds__(256) convert_split_kernel(
    const float* __restrict__ src,
    __half* __restrict__ h, __half* __restrict__ l, int n8)
{
    int i = blockIdx.x * blockDim.x + threadIdx.x;
    if (i >= n8) return;
    float4 v0 = ((const float4*)src)[2 * i];
    float4 v1 = ((const float4*)src)[2 * i + 1];
    uint4 hi, lo;
    split2h(v0.x, v0.y, hi.x, lo.x);
    split2h(v0.z, v0.w, hi.y, lo.y);
    split2h(v1.x, v1.y, hi.z, lo.z);
    split2h(v1.z, v1.w, hi.w, lo.w);
    ((uint4*)h)[i] = hi;
    ((uint4*)l)[i] = lo;
}

// Kernel 0b: fp32 -> fp16 hi only (weights)
__global__ void __launch_bounds__(256) convert_hi_kernel(
    const float* __restrict__ src, __half* __restrict__ h, int n8)
{
    int i = blockIdx.x * blockDim.x + threadIdx.x;
    if (i >= n8) return;
    float4 v0 = ((const float4*)src)[2 * i];
    float4 v1 = ((const float4*)src)[2 * i + 1];
    uint4 hi;
    hi.x = pack2h(v0.x, v0.y);
    hi.y = pack2h(v0.z, v0.w);
    hi.z = pack2h(v1.x, v1.y);
    hi.w = pack2h(v1.z, v1.w);
    ((uint4*)h)[i] = hi;
}

// ============================================================================
// Kernel 1: C[M,N] = A[M,K] @ B[N,K]^T, fp16 2-pass (Ah*Bh + Al*Bh).
// Stage = Ah | Al | Bh, each 128x32 fp16 (64B rows, chunk-XOR swizzle) = 24KB.
// ============================================================================
#define PSTAGE 24576
#define PGEMM_SMEM (3 * PSTAGE)   // 72KB

__global__ void __launch_bounds__(256, 2) gemm_f16_kernel(
    const __half* __restrict__ Ah, const __half* __restrict__ Al,
    const __half* __restrict__ Bh,
    float* __restrict__ C, int N, int K)
{
    extern __shared__ char smem[];
    const uint32_t sb = smem_u32(smem);
    const int tid = threadIdx.x;
    const int wid = tid >> 5;
    const int lane = tid & 31;
    const int m0 = blockIdx.y * 128;
    const int n0 = blockIdx.x * 128;
    const int NC = K >> 5;

    const int warp_m = wid & 3;
    const int warp_n = wid >> 2;

    const int lrow = tid >> 1;
    const int swz_l = (lrow >> 1) & 3;
    const uint32_t so0 = lrow * 64 + ((((tid & 1) * 2 + 0) ^ swz_l) << 4);
    const uint32_t so1 = lrow * 64 + ((((tid & 1) * 2 + 1) ^ swz_l) << 4);
    const size_t roA0 = (size_t)(m0 + lrow) * K + (tid & 1) * 16;
    const size_t roB0 = (size_t)(n0 + lrow) * K + (tid & 1) * 16;

    auto issue = [&](int c, int st) {
        const uint32_t base = sb + st * PSTAGE;
        const size_t ra = roA0 + c * 32;
        const size_t rb = roB0 + c * 32;
        CP16(base + so0,         Ah + ra);
        CP16(base + so1,         Ah + ra + 8);
        CP16(base + 8192 + so0,  Al + ra);
        CP16(base + 8192 + so1,  Al + ra + 8);
        CP16(base + 16384 + so0, Bh + rb);
        CP16(base + 16384 + so1, Bh + rb + 8);
    };

    uint32_t aoff[2][2];
#pragma unroll
    for (int tm = 0; tm < 2; tm++) {
        int r = warp_m * 32 + tm * 16 + (lane & 15);
        int sw = (r >> 1) & 3;
#pragma unroll
        for (int ks = 0; ks < 2; ks++) {
            int ch = ks * 2 + (lane >> 4);
            aoff[tm][ks] = r * 64 + ((ch ^ sw) << 4);
        }
    }
    uint32_t boff[4][2];
#pragma unroll
    for (int bp = 0; bp < 4; bp++) {
        int r = warp_n * 64 + bp * 16 + ((lane >> 4) << 3) + (lane & 7);
        int sw = (r >> 1) & 3;
#pragma unroll
        for (int ks = 0; ks < 2; ks++) {
            int ch = ks * 2 + ((lane >> 3) & 1);
            boff[bp][ks] = r * 64 + ((ch ^ sw) << 4);
        }
    }

    float acc[2][8][4];
#pragma unroll
    for (int i = 0; i < 2; i++)
#pragma unroll
        for (int j = 0; j < 8; j++)
#pragma unroll
            for (int q = 0; q < 4; q++) acc[i][j][q] = 0.f;

    issue(0, 0); CP_COMMIT();
    issue(1, 1); CP_COMMIT();
    issue(2, 2); CP_COMMIT();

    int st = 0;
#pragma unroll 1
    for (int bk = 0; bk < NC; bk++) {
        CP_WAIT2();
        __syncthreads();

        const uint32_t ah = sb + st * PSTAGE;
        const uint32_t al = ah + 8192;
        const uint32_t wh = ah + 16384;
#pragma unroll
        for (int ks = 0; ks < 2; ks++) {
            uint32_t fa[2][4], fal[2][4];
#pragma unroll
            for (int tm = 0; tm < 2; tm++) {
                ldsm4(fa[tm], ah + aoff[tm][ks]);
                ldsm4(fal[tm], al + aoff[tm][ks]);
            }
            uint32_t fb[8][2];
#pragma unroll
            for (int bp = 0; bp < 4; bp++) {
                uint32_t t[4];
                ldsm4(t, wh + boff[bp][ks]);
                fb[2*bp][0] = t[0]; fb[2*bp][1] = t[1];
                fb[2*bp+1][0] = t[2]; fb[2*bp+1][1] = t[3];
            }
#pragma unroll
            for (int tm = 0; tm < 2; tm++)
#pragma unroll
                for (int tn = 0; tn < 8; tn++)
                    mma_f16(acc[tm][tn], fa[tm], fb[tn]);     // hi*hi
#pragma unroll
            for (int tm = 0; tm < 2; tm++)
#pragma unroll
                for (int tn = 0; tn < 8; tn++)
                    mma_f16(acc[tm][tn], fal[tm], fb[tn]);    // lo*hi
        }

        __syncthreads();
        if (bk + 3 < NC) issue(bk + 3, st);
        CP_COMMIT();
        st = (st == 2) ? 0 : st + 1;
    }

    const int er = lane >> 2;
    const int ec = (lane & 3) * 2;
#pragma unroll
    for (int tm = 0; tm < 2; tm++) {
        const int rbase = m0 + warp_m * 32 + tm * 16 + er;
#pragma unroll
        for (int tn = 0; tn < 8; tn++) {
            const int cbase = n0 + warp_n * 64 + tn * 8 + ec;
            float* p0 = C + (size_t)rbase * N + cbase;
            float* p1 = C + (size_t)(rbase + 8) * N + cbase;
            *(float2*)p0 = make_float2(acc[tm][tn][0], acc[tm][tn][1]);
            *(float2*)p1 = make_float2(acc[tm][tn][2], acc[tm][tn][3]);
        }
    }
}

// ============================================================================
// Kernel 2: qk-norm + RoPE2D + transpose -> fp16 outputs.
// q: single fp16 (scores only need absolute accuracy; scale folded in).
// k: single fp16. v: fp16 hi/lo, transposed [b,g,d,l].
// ============================================================================
__global__ void __launch_bounds__(256) norm_rope_kernel(
    const float* __restrict__ qkv,
    __half* __restrict__ qh, __half* __restrict__ kh,
    __half* __restrict__ vth, __half* __restrict__ vtl)
{
    const int gwarp = (blockIdx.x * blockDim.x + threadIdx.x) >> 5;
    const int lane = threadIdx.x & 31;
    const int NVEC = MROWS * 24;
    if (gwarp >= NVEC) return;

    const int bl = gwarp / 24;
    const int slot = gwarp % 24;
    const int b = bl >> 10;
    const int l = bl & 1023;

    const float2 xv = *(const float2*)(qkv + (size_t)bl * QKV_E + slot * 64 + 2 * lane);
    float x1 = xv.x, x2 = xv.y;

    if (slot < 20) {
        float ss = x1 * x1 + x2 * x2;
#pragma unroll
        for (int o = 16; o > 0; o >>= 1)
            ss += __shfl_xor_sync(0xffffffffu, ss, o);
        float inv = 1.f / (sqrtf(ss) + 1e-10f);
        if (slot < 16) inv *= 0.18033688011112042f;  // 0.125 * log2(e)
        x1 *= inv; x2 *= inv;

        float psum = (float)((l >> 5) + (l & 31));
        float invfreq = exp2f(-0.41524101186098287f * (float)lane);
        float fr = psum * invfreq;
        float s, c;
        sincosf(fr, &s, &c);
        float olo = x1 * c - x2 * s;
        float ohi = x1 * s + x2 * c;

        __half* dst;
        if (slot < 16)
            dst = qh + (((size_t)b * NH + slot) * L_SZ + l) * HD;
        else
            dst = kh + (((size_t)b * NG + (slot - 16)) * L_SZ + l) * HD;
        dst[lane] = __float2half_rn(olo);
        dst[lane + 32] = __float2half_rn(ohi);
    } else {
        const int sv = slot - 20;
        const size_t base = ((size_t)b * NG + sv) * HD * L_SZ;
        __half h, lo;
        split1h(x1, h, lo);
        vth[base + (size_t)(2 * lane) * L_SZ + l] = h;
        vtl[base + (size_t)(2 * lane) * L_SZ + l] = lo;
        split1h(x2, h, lo);
        vth[base + (size_t)(2 * lane + 1) * L_SZ + l] = h;
        vtl[base + (size_t)(2 * lane + 1) * L_SZ + l] = lo;
    }
}

// ============================================================================
// Kernel 3: tensor-core flash attention (fp16).
// S: 1 pass (Qh*Kh). PV: 2 passes (P*Vh + P*Vl).
// Q smem 16KB; stage = KH 8K | VH 8K | VL 8K = 24KB x 2 stages. Total 64KB.
// ============================================================================
#define A_OFF_QH 0
#define A_OFF_KV 16384
#define A_STAGE  24576
#define ATTN_SMEM (A_OFF_KV + 2 * A_STAGE)   // 65536

__global__ void __launch_bounds__(256, 2) attn_f16_kernel(
    const __half* __restrict__ qh, const __half* __restrict__ kh,
    const __half* __restrict__ vth, const __half* __restrict__ vtl,
    __half* __restrict__ Oh, __half* __restrict__ Ol)
{
    extern __shared__ char smem[];
    const uint32_t sb = smem_u32(smem);
    const int tid = threadIdx.x;
    const int wid = tid >> 5;
    const int lane = tid & 31;

    const int qt = blockIdx.x;
    const int h = blockIdx.y;
    const int b = blockIdx.z;
    const int g = h >> 2;

    const __half* Qh_g = qh + ((((size_t)b * NH + h) * L_SZ) + qt * 128) * HD;
    const __half* Kh_g = kh + (((size_t)b * NG + g) * L_SZ) * HD;
    const __half* Vth_g = vth + ((size_t)b * NG + g) * HD * L_SZ;
    const __half* Vtl_g = vtl + ((size_t)b * NG + g) * HD * L_SZ;

    // ---- issue Q (once): 16KB = 1024 chunks, 4 per thread ----
#pragma unroll
    for (int i = 0; i < 4; i++) {
        int idx = tid * 4 + i;
        int row = idx >> 3, ch = idx & 7;
        uint32_t sw = (uint32_t)(row * 128 + ((ch ^ (row & 7)) << 4));
        CP16(sb + A_OFF_QH + sw, Qh_g + row * 64 + ch * 8);
    }

    auto issue_chunk = [&](int c, int st) {
        const uint32_t base = sb + A_OFF_KV + st * A_STAGE;
#pragma unroll
        for (int i = 0; i < 2; i++) {
            int idx = tid * 2 + i;
            int row = idx >> 3, ch = idx & 7;
            uint32_t sw = (uint32_t)(row * 128 + ((ch ^ (row & 7)) << 4));
            CP16(base + sw,         Kh_g + (size_t)(c * 64 + row) * 64 + ch * 8);
            CP16(base + 8192 + sw,  Vth_g + (size_t)row * L_SZ + c * 64 + ch * 8);
            CP16(base + 16384 + sw, Vtl_g + (size_t)row * L_SZ + c * 64 + ch * 8);
        }
    };

    issue_chunk(0, 0);
    CP_COMMIT();
    issue_chunk(1, 1);
    CP_COMMIT();

    uint32_t qoff[4];
#pragma unroll
    for (int ks = 0; ks < 4; ks++) {
        int r = wid * 16 + (lane & 15);
        int ch = ks * 2 + (lane >> 4);
        qoff[ks] = (uint32_t)(r * 128 + ((ch ^ (r & 7)) << 4));
    }
    uint32_t lbo[4][4];
#pragma unroll
    for (int np = 0; np < 4; np++) {
        int r = np * 16 + ((lane >> 4) << 3) + (lane & 7);
#pragma unroll
        for (int ks = 0; ks < 4; ks++) {
            int ch = ks * 2 + ((lane >> 3) & 1);
            lbo[np][ks] = (uint32_t)(r * 128 + ((ch ^ (r & 7)) << 4));
        }
    }

    uint32_t qfh[4][4];
    float oacc[8][4];
#pragma unroll
    for (int t = 0; t < 8; t++)
#pragma unroll
        for (int q = 0; q < 4; q++) oacc[t][q] = 0.f;
    float mrow[2] = {-INFINITY, -INFINITY};
    float lrow[2] = {0.f, 0.f};

#pragma unroll 1
    for (int c = 0; c < 16; c++) {
        const int st = c & 1;
        CP_WAIT1();
        __syncthreads();

        if (c == 0) {
#pragma unroll
            for (int ks = 0; ks < 4; ks++)
                ldsm4(qfh[ks], sb + A_OFF_QH + qoff[ks]);
        }

        const uint32_t kb = sb + A_OFF_KV + st * A_STAGE;
        const uint32_t vbh = kb + 8192;
        const uint32_t vbl = kb + 16384;

        // ---- S = Q K^T, single fp16 pass ----
        float sacc[8][4];
#pragma unroll
        for (int t = 0; t < 8; t++)
#pragma unroll
            for (int q = 0; q < 4; q++) sacc[t][q] = 0.f;
#pragma unroll
        for (int ks = 0; ks < 4; ks++) {
            uint32_t kth[4][4];
#pragma unroll
            for (int np = 0; np < 4; np++)
                ldsm4(kth[np], kb + lbo[np][ks]);
#pragma unroll
            for (int np = 0; np < 4; np++) {
                mma_f16(sacc[2*np],   qfh[ks], kth[np]);
                mma_f16(sacc[2*np+1], qfh[ks], kth[np] + 2);
            }
        }

        // ---- online softmax (log2 domain) ----
#pragma unroll
        for (int r = 0; r < 2; r++) {
            float mx = mrow[r];
#pragma unroll
            for (int t = 0; t < 8; t++)
                mx = fmaxf(mx, fmaxf(sacc[t][2*r], sacc[t][2*r+1]));
            mx = fmaxf(mx, __shfl_xor_sync(0xffffffffu, mx, 1));
            mx = fmaxf(mx, __shfl_xor_sync(0xffffffffu, mx, 2));
            const float sc = exp2f(mrow[r] - mx);
            mrow[r] = mx;
            float sum = 0.f;
#pragma unroll
            for (int t = 0; t < 8; t++) {
                float p0 = exp2f(sacc[t][2*r]   - mx);
                float p1 = exp2f(sacc[t][2*r+1] - mx);
                sacc[t][2*r] = p0; sacc[t][2*r+1] = p1;
                sum += p0 + p1;
            }
            sum += __shfl_xor_sync(0xffffffffu, sum, 1);
            sum += __shfl_xor_sync(0xffffffffu, sum, 2);
            lrow[r] = lrow[r] * sc + sum;
#pragma unroll
            for (int t = 0; t < 8; t++) {
                oacc[t][2*r] *= sc; oacc[t][2*r+1] *= sc;
            }
        }

        // ---- O += P V  (P single fp16; V hi + lo passes) ----
#pragma unroll
        for (int j = 0; j < 4; j++) {
            uint32_t pah[4];
            pah[0] = pack2h(sacc[2*j][0],   sacc[2*j][1]);
            pah[1] = pack2h(sacc[2*j][2],   sacc[2*j][3]);
            pah[2] = pack2h(sacc[2*j+1][0], sacc[2*j+1][1]);
            pah[3] = pack2h(sacc[2*j+1][2], sacc[2*j+1][3]);
            uint32_t vfh[4][4], vfl[4][4];
#pragma unroll
            for (int dp = 0; dp < 4; dp++) {
                ldsm4(vfh[dp], vbh + lbo[dp][j]);
                ldsm4(vfl[dp], vbl + lbo[dp][j]);
            }
#pragma unroll
            for (int dp = 0; dp < 4; dp++) {
                mma_f16(oacc[2*dp],   pah, vfh[dp]);
                mma_f16(oacc[2*dp+1], pah, vfh[dp] + 2);
            }
#pragma unroll
            for (int dp = 0; dp < 4; dp++) {
                mma_f16(oacc[2*dp],   pah, vfl[dp]);
                mma_f16(oacc[2*dp+1], pah, vfl[dp] + 2);
            }
        }

        __syncthreads();
        if (c + 2 < 16) issue_chunk(c + 2, st);
        CP_COMMIT();
    }

    // ---- normalize + split to fp16 hi/lo, write [b, l, h*64+d] ----
    const float inv0 = 1.f / lrow[0];
    const float inv1 = 1.f / lrow[1];
    const int q0 = qt * 128 + wid * 16 + (lane >> 2);
#pragma unroll
    for (int t = 0; t < 8; t++) {
        const int col = h * 64 + t * 8 + (lane & 3) * 2;
        const size_t o0 = ((size_t)(b * L_SZ + q0)) * DM + col;
        const size_t o1 = ((size_t)(b * L_SZ + q0 + 8)) * DM + col;
        uint32_t hi, lo;
        split2h(oacc[t][0] * inv0, oacc[t][1] * inv0, hi, lo);
        *(uint32_t*)(Oh + o0) = hi;
        *(uint32_t*)(Ol + o0) = lo;
        split2h(oacc[t][2] * inv1, oacc[t][3] * inv1, hi, lo);
        *(uint32_t*)(Oh + o1) = hi;
        *(uint32_t*)(Ol + o1) = lo;
    }
}

// ============================================================================
// launch
// ============================================================================
extern "C" void kernel_launch(void* const* d_in, const int* in_sizes, int n_in,
                              void* d_out, int out_size)
{
    const float* x     = (const float*)d_in[0];
    const float* w_qkv = (const float*)d_in[1];
    const float* w_o   = (const float*)d_in[2];
    float* out = (float*)d_out;

    float* qkv_p;
    __half *xh_p, *xl_p, *wqh_p, *woh_p, *ah_p, *al_p;
    __half *qh_p, *kh_p, *vth_p, *vtl_p;
    cudaGetSymbolAddress((void**)&qkv_p, g_qkv);
    cudaGetSymbolAddress((void**)&xh_p,  g_xh);
    cudaGetSymbolAddress((void**)&xl_p,  g_xl);
    cudaGetSymbolAddress((void**)&wqh_p, g_wqh);
    cudaGetSymbolAddress((void**)&woh_p, g_woh);
    cudaGetSymbolAddress((void**)&ah_p,  g_ah);
    cudaGetSymbolAddress((void**)&al_p,  g_al);
    cudaGetSymbolAddress((void**)&qh_p,  g_qh);
    cudaGetSymbolAddress((void**)&kh_p,  g_kh);
    cudaGetSymbolAddress((void**)&vth_p, g_vth);
    cudaGetSymbolAddress((void**)&vtl_p, g_vtl);

    cudaFuncSetAttribute(gemm_f16_kernel,
                         cudaFuncAttributeMaxDynamicSharedMemorySize, PGEMM_SMEM);
    cudaFuncSetAttribute(attn_f16_kernel,
                         cudaFuncAttributeMaxDynamicSharedMemorySize, ATTN_SMEM);

    convert_split_kernel<<<(MROWS * DM / 8 + 255) / 256, 256>>>(x, xh_p, xl_p, MROWS * DM / 8);
    convert_hi_kernel<<<(QKV_E * DM / 8 + 255) / 256, 256>>>(w_qkv, wqh_p, QKV_E * DM / 8);
    convert_hi_kernel<<<(DM * DM / 8 + 255) / 256, 256>>>(w_o, woh_p, DM * DM / 8);

    // 1) QKV projection
    {
        dim3 grid(QKV_E / 128, MROWS / 128);
        gemm_f16_kernel<<<grid, 256, PGEMM_SMEM>>>(xh_p, xl_p, wqh_p,
                                                   qkv_p, QKV_E, DM);
    }
    // 2) norm + rope
    {
        int nvec = MROWS * 24;
        int blocks = (nvec + 7) / 8;
        norm_rope_kernel<<<blocks, 256>>>(qkv_p, qh_p, kh_p, vth_p, vtl_p);
    }
    // 3) attention
    {
        dim3 grid(L_SZ / 128, NH, B_SZ);
        attn_f16_kernel<<<grid, 256, ATTN_SMEM>>>(qh_p, kh_p, vth_p, vtl_p,
                                                  ah_p, al_p);
    }
    // 4) output projection
    {
        dim3 grid(DM / 128, MROWS / 128);
        gemm_f16_kernel<<<grid, 256, PGEMM_SMEM>>>(ah_p, al_p, woh_p,
                                                   out, DM, DM);
    }
}

// round 9
// speedup vs baseline: 2.2858x; 1.5247x over previous
#include <cuda_runtime.h>
#include <cuda_fp16.h>
#include <math.h>
#include <stdint.h>

// Problem constants
#define B_SZ 8
#define L_SZ 1024
#define DM 1024
#define NH 16
#define NG 4
#define HD 64
#define QKV_E 1536
#define MROWS (B_SZ * L_SZ)   // 8192

// ---------------- scratch (device globals; no allocation allowed) ----------
__device__ float g_qkv[MROWS * QKV_E];
__device__ __half g_xh[MROWS * DM];
__device__ __half g_wqh[QKV_E * DM];
__device__ __half g_woh[DM * DM];
__device__ __half g_ah[MROWS * DM];              // attention output
__device__ __half g_qh[B_SZ * NH * L_SZ * HD];
__device__ __half g_kh[B_SZ * NG * L_SZ * HD];
__device__ __half g_vth[B_SZ * NG * HD * L_SZ];  // [b,g,d,l]

// ============================================================================
// helpers
// ============================================================================
__device__ __forceinline__ uint32_t smem_u32(const void* p) {
    uint32_t a;
    asm("{ .reg .u64 t; cvta.to.shared.u64 t, %1; cvt.u32.u64 %0, t; }"
        : "=r"(a) : "l"(p));
    return a;
}

__device__ __forceinline__ void ldsm4(uint32_t* r, uint32_t addr) {
    asm volatile("ldmatrix.sync.aligned.m8n8.x4.shared.b16 {%0,%1,%2,%3}, [%4];"
        : "=r"(r[0]), "=r"(r[1]), "=r"(r[2]), "=r"(r[3]) : "r"(addr));
}

__device__ __forceinline__ void mma_f16(float* d, const uint32_t* a,
                                        const uint32_t* b) {
    asm volatile(
        "mma.sync.aligned.m16n8k16.row.col.f32.f16.f16.f32 "
        "{%0,%1,%2,%3}, {%4,%5,%6,%7}, {%8,%9}, {%0,%1,%2,%3};"
        : "+f"(d[0]), "+f"(d[1]), "+f"(d[2]), "+f"(d[3])
        : "r"(a[0]), "r"(a[1]), "r"(a[2]), "r"(a[3]), "r"(b[0]), "r"(b[1]));
}

__device__ __forceinline__ uint32_t pack2h(float a, float b) {
    __half2 h = __floats2half2_rn(a, b);
    return *(uint32_t*)&h;
}

#define CP16(smem_addr, gptr) \
    asm volatile("cp.async.cg.shared.global [%0], [%1], 16;" :: "r"(smem_addr), "l"(gptr))
#define CP_COMMIT() asm volatile("cp.async.commit_group;" ::: "memory")
#define CP_WAIT1()  asm volatile("cp.async.wait_group 1;" ::: "memory")
#define CP_WAIT3()  asm volatile("cp.async.wait_group 3;" ::: "memory")

// ============================================================================
// Kernel 0: fp32 -> fp16
// ============================================================================
__global__ void __launch_bounds__(256) convert_hi_kernel(
    const float* __restrict__ src, __half* __restrict__ h, int n8)
{
    int i = blockIdx.x * blockDim.x + threadIdx.x;
    if (i >= n8) return;
    float4 v0 = ((const float4*)src)[2 * i];
    float4 v1 = ((const float4*)src)[2 * i + 1];
    uint4 hi;
    hi.x = pack2h(v0.x, v0.y);
    hi.y = pack2h(v0.z, v0.w);
    hi.z = pack2h(v1.x, v1.y);
    hi.w = pack2h(v1.z, v1.w);
    ((uint4*)h)[i] = hi;
}

// ============================================================================
// Kernel 1: C[M,N] = A[M,K] @ B[N,K]^T, single-pass fp16, fp32 accumulate.
// 128x128 CTA tile, BK=32, 8 warps, 4-stage cp.async pipeline.
// Stage = Ah | Bh, each 128x32 fp16 (64B rows, chunk-XOR swizzle) = 16KB.
// ============================================================================
#define PSTAGE 16384
#define PGEMM_SMEM (4 * PSTAGE)   // 64KB

__global__ void __launch_bounds__(256, 2) gemm_f16_kernel(
    const __half* __restrict__ Ah, const __half* __restrict__ Bh,
    float* __restrict__ C, int N, int K)
{
    extern __shared__ char smem[];
    const uint32_t sb = smem_u32(smem);
    const int tid = threadIdx.x;
    const int wid = tid >> 5;
    const int lane = tid & 31;
    const int m0 = blockIdx.y * 128;
    const int n0 = blockIdx.x * 128;
    const int NC = K >> 5;

    const int warp_m = wid & 3;
    const int warp_n = wid >> 2;

    const int lrow = tid >> 1;
    const int swz_l = (lrow >> 1) & 3;
    const uint32_t so0 = lrow * 64 + ((((tid & 1) * 2 + 0) ^ swz_l) << 4);
    const uint32_t so1 = lrow * 64 + ((((tid & 1) * 2 + 1) ^ swz_l) << 4);
    const size_t roA0 = (size_t)(m0 + lrow) * K + (tid & 1) * 16;
    const size_t roB0 = (size_t)(n0 + lrow) * K + (tid & 1) * 16;

    auto issue = [&](int c, int st) {
        const uint32_t base = sb + st * PSTAGE;
        const size_t ra = roA0 + c * 32;
        const size_t rb = roB0 + c * 32;
        CP16(base + so0,        Ah + ra);
        CP16(base + so1,        Ah + ra + 8);
        CP16(base + 8192 + so0, Bh + rb);
        CP16(base + 8192 + so1, Bh + rb + 8);
    };

    uint32_t aoff[2][2];
#pragma unroll
    for (int tm = 0; tm < 2; tm++) {
        int r = warp_m * 32 + tm * 16 + (lane & 15);
        int sw = (r >> 1) & 3;
#pragma unroll
        for (int ks = 0; ks < 2; ks++) {
            int ch = ks * 2 + (lane >> 4);
            aoff[tm][ks] = r * 64 + ((ch ^ sw) << 4);
        }
    }
    uint32_t boff[4][2];
#pragma unroll
    for (int bp = 0; bp < 4; bp++) {
        int r = warp_n * 64 + bp * 16 + ((lane >> 4) << 3) + (lane & 7);
        int sw = (r >> 1) & 3;
#pragma unroll
        for (int ks = 0; ks < 2; ks++) {
            int ch = ks * 2 + ((lane >> 3) & 1);
            boff[bp][ks] = r * 64 + ((ch ^ sw) << 4);
        }
    }

    float acc[2][8][4];
#pragma unroll
    for (int i = 0; i < 2; i++)
#pragma unroll
        for (int j = 0; j < 8; j++)
#pragma unroll
            for (int q = 0; q < 4; q++) acc[i][j][q] = 0.f;

    issue(0, 0); CP_COMMIT();
    issue(1, 1); CP_COMMIT();
    issue(2, 2); CP_COMMIT();
    issue(3, 3); CP_COMMIT();

    int st = 0;
#pragma unroll 1
    for (int bk = 0; bk < NC; bk++) {
        CP_WAIT3();
        __syncthreads();

        const uint32_t ah = sb + st * PSTAGE;
        const uint32_t wh = ah + 8192;
#pragma unroll
        for (int ks = 0; ks < 2; ks++) {
            uint32_t fa[2][4];
#pragma unroll
            for (int tm = 0; tm < 2; tm++)
                ldsm4(fa[tm], ah + aoff[tm][ks]);
            uint32_t fb[8][2];
#pragma unroll
            for (int bp = 0; bp < 4; bp++) {
                uint32_t t[4];
                ldsm4(t, wh + boff[bp][ks]);
                fb[2*bp][0] = t[0]; fb[2*bp][1] = t[1];
                fb[2*bp+1][0] = t[2]; fb[2*bp+1][1] = t[3];
            }
#pragma unroll
            for (int tm = 0; tm < 2; tm++)
#pragma unroll
                for (int tn = 0; tn < 8; tn++)
                    mma_f16(acc[tm][tn], fa[tm], fb[tn]);
        }

        __syncthreads();
        if (bk + 4 < NC) issue(bk + 4, st);
        CP_COMMIT();
        st = (st + 1) & 3;
    }

    const int er = lane >> 2;
    const int ec = (lane & 3) * 2;
#pragma unroll
    for (int tm = 0; tm < 2; tm++) {
        const int rbase = m0 + warp_m * 32 + tm * 16 + er;
#pragma unroll
        for (int tn = 0; tn < 8; tn++) {
            const int cbase = n0 + warp_n * 64 + tn * 8 + ec;
            float* p0 = C + (size_t)rbase * N + cbase;
            float* p1 = C + (size_t)(rbase + 8) * N + cbase;
            *(float2*)p0 = make_float2(acc[tm][tn][0], acc[tm][tn][1]);
            *(float2*)p1 = make_float2(acc[tm][tn][2], acc[tm][tn][3]);
        }
    }
}

// ============================================================================
// Kernel 2: qk-norm + RoPE2D + transpose -> fp16 outputs (all single fp16).
// q gets 0.125 * log2(e) folded in (softmax uses exp2).
// v written transposed [b,g,d,l].
// ============================================================================
__global__ void __launch_bounds__(256) norm_rope_kernel(
    const float* __restrict__ qkv,
    __half* __restrict__ qh, __half* __restrict__ kh,
    __half* __restrict__ vth)
{
    const int gwarp = (blockIdx.x * blockDim.x + threadIdx.x) >> 5;
    const int lane = threadIdx.x & 31;
    const int NVEC = MROWS * 24;
    if (gwarp >= NVEC) return;

    const int bl = gwarp / 24;
    const int slot = gwarp % 24;
    const int b = bl >> 10;
    const int l = bl & 1023;

    const float2 xv = *(const float2*)(qkv + (size_t)bl * QKV_E + slot * 64 + 2 * lane);
    float x1 = xv.x, x2 = xv.y;

    if (slot < 20) {
        float ss = x1 * x1 + x2 * x2;
#pragma unroll
        for (int o = 16; o > 0; o >>= 1)
            ss += __shfl_xor_sync(0xffffffffu, ss, o);
        float inv = 1.f / (sqrtf(ss) + 1e-10f);
        if (slot < 16) inv *= 0.18033688011112042f;  // 0.125 * log2(e)
        x1 *= inv; x2 *= inv;

        float psum = (float)((l >> 5) + (l & 31));
        float invfreq = exp2f(-0.41524101186098287f * (float)lane);
        float fr = psum * invfreq;
        float s, c;
        sincosf(fr, &s, &c);
        float olo = x1 * c - x2 * s;
        float ohi = x1 * s + x2 * c;

        __half* dst;
        if (slot < 16)
            dst = qh + (((size_t)b * NH + slot) * L_SZ + l) * HD;
        else
            dst = kh + (((size_t)b * NG + (slot - 16)) * L_SZ + l) * HD;
        dst[lane] = __float2half_rn(olo);
        dst[lane + 32] = __float2half_rn(ohi);
    } else {
        const int sv = slot - 20;
        const size_t base = ((size_t)b * NG + sv) * HD * L_SZ;
        vth[base + (size_t)(2 * lane) * L_SZ + l] = __float2half_rn(x1);
        vth[base + (size_t)(2 * lane + 1) * L_SZ + l] = __float2half_rn(x2);
    }
}

// ============================================================================
// Kernel 3: tensor-core flash attention, all single-pass fp16.
// Q smem 16KB; stage = KH 8K | VH 8K = 16KB x 2 stages. Total 48KB.
// ============================================================================
#define A_OFF_QH 0
#define A_OFF_KV 16384
#define A_STAGE  16384
#define ATTN_SMEM (A_OFF_KV + 2 * A_STAGE)   // 49152

__global__ void __launch_bounds__(256, 2) attn_f16_kernel(
    const __half* __restrict__ qh, const __half* __restrict__ kh,
    const __half* __restrict__ vth,
    __half* __restrict__ Oh)
{
    extern __shared__ char smem[];
    const uint32_t sb = smem_u32(smem);
    const int tid = threadIdx.x;
    const int wid = tid >> 5;
    const int lane = tid & 31;

    const int qt = blockIdx.x;
    const int h = blockIdx.y;
    const int b = blockIdx.z;
    const int g = h >> 2;

    const __half* Qh_g = qh + ((((size_t)b * NH + h) * L_SZ) + qt * 128) * HD;
    const __half* Kh_g = kh + (((size_t)b * NG + g) * L_SZ) * HD;
    const __half* Vth_g = vth + ((size_t)b * NG + g) * HD * L_SZ;

    // ---- issue Q (once): 16KB = 1024 chunks, 4 per thread ----
#pragma unroll
    for (int i = 0; i < 4; i++) {
        int idx = tid * 4 + i;
        int row = idx >> 3, ch = idx & 7;
        uint32_t sw = (uint32_t)(row * 128 + ((ch ^ (row & 7)) << 4));
        CP16(sb + A_OFF_QH + sw, Qh_g + row * 64 + ch * 8);
    }

    auto issue_chunk = [&](int c, int st) {
        const uint32_t base = sb + A_OFF_KV + st * A_STAGE;
#pragma unroll
        for (int i = 0; i < 2; i++) {
            int idx = tid * 2 + i;
            int row = idx >> 3, ch = idx & 7;
            uint32_t sw = (uint32_t)(row * 128 + ((ch ^ (row & 7)) << 4));
            CP16(base + sw,        Kh_g + (size_t)(c * 64 + row) * 64 + ch * 8);
            CP16(base + 8192 + sw, Vth_g + (size_t)row * L_SZ + c * 64 + ch * 8);
        }
    };

    issue_chunk(0, 0);
    CP_COMMIT();
    issue_chunk(1, 1);
    CP_COMMIT();

    uint32_t qoff[4];
#pragma unroll
    for (int ks = 0; ks < 4; ks++) {
        int r = wid * 16 + (lane & 15);
        int ch = ks * 2 + (lane >> 4);
        qoff[ks] = (uint32_t)(r * 128 + ((ch ^ (r & 7)) << 4));
    }
    uint32_t lbo[4][4];
#pragma unroll
    for (int np = 0; np < 4; np++) {
        int r = np * 16 + ((lane >> 4) << 3) + (lane & 7);
#pragma unroll
        for (int ks = 0; ks < 4; ks++) {
            int ch = ks * 2 + ((lane >> 3) & 1);
            lbo[np][ks] = (uint32_t)(r * 128 + ((ch ^ (r & 7)) << 4));
        }
    }

    uint32_t qfh[4][4];
    float oacc[8][4];
#pragma unroll
    for (int t = 0; t < 8; t++)
#pragma unroll
        for (int q = 0; q < 4; q++) oacc[t][q] = 0.f;
    float mrow[2] = {-INFINITY, -INFINITY};
    float lrow[2] = {0.f, 0.f};

#pragma unroll 1
    for (int c = 0; c < 16; c++) {
        const int st = c & 1;
        CP_WAIT1();
        __syncthreads();

        if (c == 0) {
#pragma unroll
            for (int ks = 0; ks < 4; ks++)
                ldsm4(qfh[ks], sb + A_OFF_QH + qoff[ks]);
        }

        const uint32_t kb = sb + A_OFF_KV + st * A_STAGE;
        const uint32_t vbh = kb + 8192;

        // ---- S = Q K^T ----
        float sacc[8][4];
#pragma unroll
        for (int t = 0; t < 8; t++)
#pragma unroll
            for (int q = 0; q < 4; q++) sacc[t][q] = 0.f;
#pragma unroll
        for (int ks = 0; ks < 4; ks++) {
            uint32_t kth[4][4];
#pragma unroll
            for (int np = 0; np < 4; np++)
                ldsm4(kth[np], kb + lbo[np][ks]);
#pragma unroll
            for (int np = 0; np < 4; np++) {
                mma_f16(sacc[2*np],   qfh[ks], kth[np]);
                mma_f16(sacc[2*np+1], qfh[ks], kth[np] + 2);
            }
        }

        // ---- online softmax (log2 domain) ----
#pragma unroll
        for (int r = 0; r < 2; r++) {
            float mx = mrow[r];
#pragma unroll
            for (int t = 0; t < 8; t++)
                mx = fmaxf(mx, fmaxf(sacc[t][2*r], sacc[t][2*r+1]));
            mx = fmaxf(mx, __shfl_xor_sync(0xffffffffu, mx, 1));
            mx = fmaxf(mx, __shfl_xor_sync(0xffffffffu, mx, 2));
            const float sc = exp2f(mrow[r] - mx);
            mrow[r] = mx;
            float sum = 0.f;
#pragma unroll
            for (int t = 0; t < 8; t++) {
                float p0 = exp2f(sacc[t][2*r]   - mx);
                float p1 = exp2f(sacc[t][2*r+1] - mx);
                sacc[t][2*r] = p0; sacc[t][2*r+1] = p1;
                sum += p0 + p1;
            }
            sum += __shfl_xor_sync(0xffffffffu, sum, 1);
            sum += __shfl_xor_sync(0xffffffffu, sum, 2);
            lrow[r] = lrow[r] * sc + sum;
#pragma unroll
            for (int t = 0; t < 8; t++) {
                oacc[t][2*r] *= sc; oacc[t][2*r+1] *= sc;
            }
        }

        // ---- O += P V (single pass) ----
#pragma unroll
        for (int j = 0; j < 4; j++) {
            uint32_t pah[4];
            pah[0] = pack2h(sacc[2*j][0],   sacc[2*j][1]);
            pah[1] = pack2h(sacc[2*j][2],   sacc[2*j][3]);
            pah[2] = pack2h(sacc[2*j+1][0], sacc[2*j+1][1]);
            pah[3] = pack2h(sacc[2*j+1][2], sacc[2*j+1][3]);
            uint32_t vfh[4][4];
#pragma unroll
            for (int dp = 0; dp < 4; dp++)
                ldsm4(vfh[dp], vbh + lbo[dp][j]);
#pragma unroll
            for (int dp = 0; dp < 4; dp++) {
                mma_f16(oacc[2*dp],   pah, vfh[dp]);
                mma_f16(oacc[2*dp+1], pah, vfh[dp] + 2);
            }
        }

        __syncthreads();
        if (c + 2 < 16) issue_chunk(c + 2, st);
        CP_COMMIT();
    }

    // ---- normalize + write fp16 [b, l, h*64+d] ----
    const float inv0 = 1.f / lrow[0];
    const float inv1 = 1.f / lrow[1];
    const int q0 = qt * 128 + wid * 16 + (lane >> 2);
#pragma unroll
    for (int t = 0; t < 8; t++) {
        const int col = h * 64 + t * 8 + (lane & 3) * 2;
        const size_t o0 = ((size_t)(b * L_SZ + q0)) * DM + col;
        const size_t o1 = ((size_t)(b * L_SZ + q0 + 8)) * DM + col;
        *(uint32_t*)(Oh + o0) = pack2h(oacc[t][0] * inv0, oacc[t][1] * inv0);
        *(uint32_t*)(Oh + o1) = pack2h(oacc[t][2] * inv1, oacc[t][3] * inv1);
    }
}

// ============================================================================
// launch
// ============================================================================
extern "C" void kernel_launch(void* const* d_in, const int* in_sizes, int n_in,
                              void* d_out, int out_size)
{
    const float* x     = (const float*)d_in[0];
    const float* w_qkv = (const float*)d_in[1];
    const float* w_o   = (const float*)d_in[2];
    float* out = (float*)d_out;

    float* qkv_p;
    __half *xh_p, *wqh_p, *woh_p, *ah_p;
    __half *qh_p, *kh_p, *vth_p;
    cudaGetSymbolAddress((void**)&qkv_p, g_qkv);
    cudaGetSymbolAddress((void**)&xh_p,  g_xh);
    cudaGetSymbolAddress((void**)&wqh_p, g_wqh);
    cudaGetSymbolAddress((void**)&woh_p, g_woh);
    cudaGetSymbolAddress((void**)&ah_p,  g_ah);
    cudaGetSymbolAddress((void**)&qh_p,  g_qh);
    cudaGetSymbolAddress((void**)&kh_p,  g_kh);
    cudaGetSymbolAddress((void**)&vth_p, g_vth);

    cudaFuncSetAttribute(gemm_f16_kernel,
                         cudaFuncAttributeMaxDynamicSharedMemorySize, PGEMM_SMEM);
    cudaFuncSetAttribute(attn_f16_kernel,
                         cudaFuncAttributeMaxDynamicSharedMemorySize, ATTN_SMEM);

    convert_hi_kernel<<<(MROWS * DM / 8 + 255) / 256, 256>>>(x, xh_p, MROWS * DM / 8);
    convert_hi_kernel<<<(QKV_E * DM / 8 + 255) / 256, 256>>>(w_qkv, wqh_p, QKV_E * DM / 8);
    convert_hi_kernel<<<(DM * DM / 8 + 255) / 256, 256>>>(w_o, woh_p, DM * DM / 8);

    // 1) QKV projection (single-pass fp16)
    {
        dim3 grid(QKV_E / 128, MROWS / 128);
        gemm_f16_kernel<<<grid, 256, PGEMM_SMEM>>>(xh_p, wqh_p, qkv_p, QKV_E, DM);
    }
    // 2) norm + rope
    {
        int nvec = MROWS * 24;
        int blocks = (nvec + 7) / 8;
        norm_rope_kernel<<<blocks, 256>>>(qkv_p, qh_p, kh_p, vth_p);
    }
    // 3) attention
    {
        dim3 grid(L_SZ / 128, NH, B_SZ);
        attn_f16_kernel<<<grid, 256, ATTN_SMEM>>>(qh_p, kh_p, vth_p, ah_p);
    }
    // 4) output projection (single-pass fp16)
    {
        dim3 grid(DM / 128, MROWS / 128);
        gemm_f16_kernel<<<grid, 256, PGEMM_SMEM>>>(ah_p, woh_p, out, DM, DM);
    }
}

// round 10
// speedup vs baseline: 2.4353x; 1.0654x over previous
#include <cuda_runtime.h>
#include <cuda_fp16.h>
#include <math.h>
#include <stdint.h>

// Problem constants
#define B_SZ 8
#define L_SZ 1024
#define DM 1024
#define NH 16
#define NG 4
#define HD 64
#define QKV_E 1536
#define MROWS (B_SZ * L_SZ)   // 8192

// ---------------- scratch (device globals; no allocation allowed) ----------
__device__ __half g_xh[MROWS * DM];
__device__ __half g_wqh[QKV_E * DM];
__device__ __half g_woh[DM * DM];
__device__ __half g_ah[MROWS * DM];              // attention output
__device__ __half g_qh[B_SZ * NH * L_SZ * HD];
__device__ __half g_kh[B_SZ * NG * L_SZ * HD];
__device__ __half g_vth[B_SZ * NG * HD * L_SZ];  // [b,g,d,l]

// ============================================================================
// helpers
// ============================================================================
__device__ __forceinline__ uint32_t smem_u32(const void* p) {
    uint32_t a;
    asm("{ .reg .u64 t; cvta.to.shared.u64 t, %1; cvt.u32.u64 %0, t; }"
        : "=r"(a) : "l"(p));
    return a;
}

__device__ __forceinline__ void ldsm4(uint32_t* r, uint32_t addr) {
    asm volatile("ldmatrix.sync.aligned.m8n8.x4.shared.b16 {%0,%1,%2,%3}, [%4];"
        : "=r"(r[0]), "=r"(r[1]), "=r"(r[2]), "=r"(r[3]) : "r"(addr));
}

__device__ __forceinline__ void mma_f16(float* d, const uint32_t* a,
                                        const uint32_t* b) {
    asm volatile(
        "mma.sync.aligned.m16n8k16.row.col.f32.f16.f16.f32 "
        "{%0,%1,%2,%3}, {%4,%5,%6,%7}, {%8,%9}, {%0,%1,%2,%3};"
        : "+f"(d[0]), "+f"(d[1]), "+f"(d[2]), "+f"(d[3])
        : "r"(a[0]), "r"(a[1]), "r"(a[2]), "r"(a[3]), "r"(b[0]), "r"(b[1]));
}

__device__ __forceinline__ uint32_t pack2h(float a, float b) {
    __half2 h = __floats2half2_rn(a, b);
    return *(uint32_t*)&h;
}

#define CP16(smem_addr, gptr) \
    asm volatile("cp.async.cg.shared.global [%0], [%1], 16;" :: "r"(smem_addr), "l"(gptr))
#define CP_COMMIT() asm volatile("cp.async.commit_group;" ::: "memory")
#define CP_WAIT1()  asm volatile("cp.async.wait_group 1;" ::: "memory")
#define CP_WAIT3()  asm volatile("cp.async.wait_group 3;" ::: "memory")

// ============================================================================
// Kernel 0: fp32 -> fp16
// ============================================================================
__global__ void __launch_bounds__(256) convert_hi_kernel(
    const float* __restrict__ src, __half* __restrict__ h, int n8)
{
    int i = blockIdx.x * blockDim.x + threadIdx.x;
    if (i >= n8) return;
    float4 v0 = ((const float4*)src)[2 * i];
    float4 v1 = ((const float4*)src)[2 * i + 1];
    uint4 hi;
    hi.x = pack2h(v0.x, v0.y);
    hi.y = pack2h(v0.z, v0.w);
    hi.z = pack2h(v1.x, v1.y);
    hi.w = pack2h(v1.z, v1.w);
    ((uint4*)h)[i] = hi;
}

// ============================================================================
// Shared GEMM mainloop pieces (128x128 tile, BK=32, 8 warps, 4-stage cp.async)
// ============================================================================
#define PSTAGE 16384
#define PGEMM_SMEM (4 * PSTAGE)   // 64KB

// mainloop macro-free: implemented in each kernel for clarity

// ============================================================================
// Kernel 1a: QKV GEMM with FUSED norm + RoPE2D + transpose epilogue.
// C is never materialized. slot = blockIdx.x*2 + warp_n (64-col head tile).
// q slots 0-15 -> g_qh [b,h,l,d] (0.125*log2e folded); k slots 16-19 -> g_kh;
// v slots 20-23 -> g_vth [b,g,d,l].
// ============================================================================
__global__ void __launch_bounds__(256, 2) gemm_qkv_fused_kernel(
    const __half* __restrict__ Ah, const __half* __restrict__ Bh,
    __half* __restrict__ qh, __half* __restrict__ kh, __half* __restrict__ vth)
{
    const int K = DM;
    extern __shared__ char smem[];
    const uint32_t sb = smem_u32(smem);
    const int tid = threadIdx.x;
    const int wid = tid >> 5;
    const int lane = tid & 31;
    const int m0 = blockIdx.y * 128;
    const int n0 = blockIdx.x * 128;
    const int NC = K >> 5;

    const int warp_m = wid & 3;
    const int warp_n = wid >> 2;

    const int lrow = tid >> 1;
    const int swz_l = (lrow >> 1) & 3;
    const uint32_t so0 = lrow * 64 + ((((tid & 1) * 2 + 0) ^ swz_l) << 4);
    const uint32_t so1 = lrow * 64 + ((((tid & 1) * 2 + 1) ^ swz_l) << 4);
    const size_t roA0 = (size_t)(m0 + lrow) * K + (tid & 1) * 16;
    const size_t roB0 = (size_t)(n0 + lrow) * K + (tid & 1) * 16;

    auto issue = [&](int c, int st) {
        const uint32_t base = sb + st * PSTAGE;
        const size_t ra = roA0 + c * 32;
        const size_t rb = roB0 + c * 32;
        CP16(base + so0,        Ah + ra);
        CP16(base + so1,        Ah + ra + 8);
        CP16(base + 8192 + so0, Bh + rb);
        CP16(base + 8192 + so1, Bh + rb + 8);
    };

    uint32_t aoff[2][2];
#pragma unroll
    for (int tm = 0; tm < 2; tm++) {
        int r = warp_m * 32 + tm * 16 + (lane & 15);
        int sw = (r >> 1) & 3;
#pragma unroll
        for (int ks = 0; ks < 2; ks++) {
            int ch = ks * 2 + (lane >> 4);
            aoff[tm][ks] = r * 64 + ((ch ^ sw) << 4);
        }
    }
    uint32_t boff[4][2];
#pragma unroll
    for (int bp = 0; bp < 4; bp++) {
        int r = warp_n * 64 + bp * 16 + ((lane >> 4) << 3) + (lane & 7);
        int sw = (r >> 1) & 3;
#pragma unroll
        for (int ks = 0; ks < 2; ks++) {
            int ch = ks * 2 + ((lane >> 3) & 1);
            boff[bp][ks] = r * 64 + ((ch ^ sw) << 4);
        }
    }

    float acc[2][8][4];
#pragma unroll
    for (int i = 0; i < 2; i++)
#pragma unroll
        for (int j = 0; j < 8; j++)
#pragma unroll
            for (int q = 0; q < 4; q++) acc[i][j][q] = 0.f;

    issue(0, 0); CP_COMMIT();
    issue(1, 1); CP_COMMIT();
    issue(2, 2); CP_COMMIT();
    issue(3, 3); CP_COMMIT();

    int st = 0;
#pragma unroll 1
    for (int bk = 0; bk < NC; bk++) {
        CP_WAIT3();
        __syncthreads();
        const uint32_t ah = sb + st * PSTAGE;
        const uint32_t wh = ah + 8192;
#pragma unroll
        for (int ks = 0; ks < 2; ks++) {
            uint32_t fa[2][4];
#pragma unroll
            for (int tm = 0; tm < 2; tm++)
                ldsm4(fa[tm], ah + aoff[tm][ks]);
            uint32_t fb[8][2];
#pragma unroll
            for (int bp = 0; bp < 4; bp++) {
                uint32_t t[4];
                ldsm4(t, wh + boff[bp][ks]);
                fb[2*bp][0] = t[0]; fb[2*bp][1] = t[1];
                fb[2*bp+1][0] = t[2]; fb[2*bp+1][1] = t[3];
            }
#pragma unroll
            for (int tm = 0; tm < 2; tm++)
#pragma unroll
                for (int tn = 0; tn < 8; tn++)
                    mma_f16(acc[tm][tn], fa[tm], fb[tn]);
        }
        __syncthreads();
        if (bk + 4 < NC) issue(bk + 4, st);
        CP_COMMIT();
        st = (st + 1) & 3;
    }

    // ---- FUSED epilogue: norm + rope + scatter fp16 ----
    const int er = lane >> 2;
    const int jb = lane & 3;              // j = tn*4 + jb
    const int slot = blockIdx.x * 2 + warp_n;

#pragma unroll
    for (int tm = 0; tm < 2; tm++) {
#pragma unroll
        for (int rr = 0; rr < 2; rr++) {
            const int m = m0 + warp_m * 32 + tm * 16 + er + rr * 8;
            const int b = m >> 10;
            const int l = m & 1023;
            const int q0 = 2 * rr, q1 = 2 * rr + 1;

            if (slot < 20) {
                // L2 norm over the 64 head dims (quad reduction)
                float ss = 0.f;
#pragma unroll
                for (int tn = 0; tn < 8; tn++)
                    ss += acc[tm][tn][q0] * acc[tm][tn][q0]
                        + acc[tm][tn][q1] * acc[tm][tn][q1];
                ss += __shfl_xor_sync(0xffffffffu, ss, 1);
                ss += __shfl_xor_sync(0xffffffffu, ss, 2);
                float inv = 1.f / (sqrtf(ss) + 1e-10f);
                if (slot < 16) inv *= 0.18033688011112042f;  // 0.125*log2(e)

                const float psum = (float)((l >> 5) + (l & 31));
                __half* dst;
                if (slot < 16)
                    dst = qh + (((size_t)b * NH + slot) * L_SZ + l) * HD;
                else
                    dst = kh + (((size_t)b * NG + (slot - 16)) * L_SZ + l) * HD;
#pragma unroll
                for (int tn = 0; tn < 8; tn++) {
                    const int j = tn * 4 + jb;
                    const float fr = psum * exp2f(-0.41524101186098287f * (float)j);
                    float s, c;
                    sincosf(fr, &s, &c);
                    const float x1 = acc[tm][tn][q0] * inv;
                    const float x2 = acc[tm][tn][q1] * inv;
                    dst[j]      = __float2half_rn(x1 * c - x2 * s);
                    dst[j + 32] = __float2half_rn(x1 * s + x2 * c);
                }
            } else {
                // v: straight fp16, transposed [b,g,d,l]
                __half* dst = vth + ((size_t)(b * NG + slot - 20) * HD) * L_SZ + l;
                const int ec = jb * 2;
#pragma unroll
                for (int tn = 0; tn < 8; tn++) {
                    const int d0 = tn * 8 + ec;
                    dst[(size_t)d0 * L_SZ]       = __float2half_rn(acc[tm][tn][q0]);
                    dst[(size_t)(d0 + 1) * L_SZ] = __float2half_rn(acc[tm][tn][q1]);
                }
            }
        }
    }
}

// ============================================================================
// Kernel 1b: plain GEMM (out-projection): C fp32 = A[M,K] @ B[N,K]^T
// ============================================================================
__global__ void __launch_bounds__(256, 2) gemm_f16_kernel(
    const __half* __restrict__ Ah, const __half* __restrict__ Bh,
    float* __restrict__ C, int N, int K)
{
    extern __shared__ char smem[];
    const uint32_t sb = smem_u32(smem);
    const int tid = threadIdx.x;
    const int wid = tid >> 5;
    const int lane = tid & 31;
    const int m0 = blockIdx.y * 128;
    const int n0 = blockIdx.x * 128;
    const int NC = K >> 5;

    const int warp_m = wid & 3;
    const int warp_n = wid >> 2;

    const int lrow = tid >> 1;
    const int swz_l = (lrow >> 1) & 3;
    const uint32_t so0 = lrow * 64 + ((((tid & 1) * 2 + 0) ^ swz_l) << 4);
    const uint32_t so1 = lrow * 64 + ((((tid & 1) * 2 + 1) ^ swz_l) << 4);
    const size_t roA0 = (size_t)(m0 + lrow) * K + (tid & 1) * 16;
    const size_t roB0 = (size_t)(n0 + lrow) * K + (tid & 1) * 16;

    auto issue = [&](int c, int st) {
        const uint32_t base = sb + st * PSTAGE;
        const size_t ra = roA0 + c * 32;
        const size_t rb = roB0 + c * 32;
        CP16(base + so0,        Ah + ra);
        CP16(base + so1,        Ah + ra + 8);
        CP16(base + 8192 + so0, Bh + rb);
        CP16(base + 8192 + so1, Bh + rb + 8);
    };

    uint32_t aoff[2][2];
#pragma unroll
    for (int tm = 0; tm < 2; tm++) {
        int r = warp_m * 32 + tm * 16 + (lane & 15);
        int sw = (r >> 1) & 3;
#pragma unroll
        for (int ks = 0; ks < 2; ks++) {
            int ch = ks * 2 + (lane >> 4);
            aoff[tm][ks] = r * 64 + ((ch ^ sw) << 4);
        }
    }
    uint32_t boff[4][2];
#pragma unroll
    for (int bp = 0; bp < 4; bp++) {
        int r = warp_n * 64 + bp * 16 + ((lane >> 4) << 3) + (lane & 7);
        int sw = (r >> 1) & 3;
#pragma unroll
        for (int ks = 0; ks < 2; ks++) {
            int ch = ks * 2 + ((lane >> 3) & 1);
            boff[bp][ks] = r * 64 + ((ch ^ sw) << 4);
        }
    }

    float acc[2][8][4];
#pragma unroll
    for (int i = 0; i < 2; i++)
#pragma unroll
        for (int j = 0; j < 8; j++)
#pragma unroll
            for (int q = 0; q < 4; q++) acc[i][j][q] = 0.f;

    issue(0, 0); CP_COMMIT();
    issue(1, 1); CP_COMMIT();
    issue(2, 2); CP_COMMIT();
    issue(3, 3); CP_COMMIT();

    int st = 0;
#pragma unroll 1
    for (int bk = 0; bk < NC; bk++) {
        CP_WAIT3();
        __syncthreads();
        const uint32_t ah = sb + st * PSTAGE;
        const uint32_t wh = ah + 8192;
#pragma unroll
        for (int ks = 0; ks < 2; ks++) {
            uint32_t fa[2][4];
#pragma unroll
            for (int tm = 0; tm < 2; tm++)
                ldsm4(fa[tm], ah + aoff[tm][ks]);
            uint32_t fb[8][2];
#pragma unroll
            for (int bp = 0; bp < 4; bp++) {
                uint32_t t[4];
                ldsm4(t, wh + boff[bp][ks]);
                fb[2*bp][0] = t[0]; fb[2*bp][1] = t[1];
                fb[2*bp+1][0] = t[2]; fb[2*bp+1][1] = t[3];
            }
#pragma unroll
            for (int tm = 0; tm < 2; tm++)
#pragma unroll
                for (int tn = 0; tn < 8; tn++)
                    mma_f16(acc[tm][tn], fa[tm], fb[tn]);
        }
        __syncthreads();
        if (bk + 4 < NC) issue(bk + 4, st);
        CP_COMMIT();
        st = (st + 1) & 3;
    }

    const int er = lane >> 2;
    const int ec = (lane & 3) * 2;
#pragma unroll
    for (int tm = 0; tm < 2; tm++) {
        const int rbase = m0 + warp_m * 32 + tm * 16 + er;
#pragma unroll
        for (int tn = 0; tn < 8; tn++) {
            const int cbase = n0 + warp_n * 64 + tn * 8 + ec;
            float* p0 = C + (size_t)rbase * N + cbase;
            float* p1 = C + (size_t)(rbase + 8) * N + cbase;
            *(float2*)p0 = make_float2(acc[tm][tn][0], acc[tm][tn][1]);
            *(float2*)p1 = make_float2(acc[tm][tn][2], acc[tm][tn][3]);
        }
    }
}

// ============================================================================
// Kernel 2: tensor-core flash attention (single-pass fp16, unchanged R9).
// ============================================================================
#define A_OFF_QH 0
#define A_OFF_KV 16384
#define A_STAGE  16384
#define ATTN_SMEM (A_OFF_KV + 2 * A_STAGE)   // 49152

__global__ void __launch_bounds__(256, 2) attn_f16_kernel(
    const __half* __restrict__ qh, const __half* __restrict__ kh,
    const __half* __restrict__ vth,
    __half* __restrict__ Oh)
{
    extern __shared__ char smem[];
    const uint32_t sb = smem_u32(smem);
    const int tid = threadIdx.x;
    const int wid = tid >> 5;
    const int lane = tid & 31;

    const int qt = blockIdx.x;
    const int h = blockIdx.y;
    const int b = blockIdx.z;
    const int g = h >> 2;

    const __half* Qh_g = qh + ((((size_t)b * NH + h) * L_SZ) + qt * 128) * HD;
    const __half* Kh_g = kh + (((size_t)b * NG + g) * L_SZ) * HD;
    const __half* Vth_g = vth + ((size_t)b * NG + g) * HD * L_SZ;

#pragma unroll
    for (int i = 0; i < 4; i++) {
        int idx = tid * 4 + i;
        int row = idx >> 3, ch = idx & 7;
        uint32_t sw = (uint32_t)(row * 128 + ((ch ^ (row & 7)) << 4));
        CP16(sb + A_OFF_QH + sw, Qh_g + row * 64 + ch * 8);
    }

    auto issue_chunk = [&](int c, int st) {
        const uint32_t base = sb + A_OFF_KV + st * A_STAGE;
#pragma unroll
        for (int i = 0; i < 2; i++) {
            int idx = tid * 2 + i;
            int row = idx >> 3, ch = idx & 7;
            uint32_t sw = (uint32_t)(row * 128 + ((ch ^ (row & 7)) << 4));
            CP16(base + sw,        Kh_g + (size_t)(c * 64 + row) * 64 + ch * 8);
            CP16(base + 8192 + sw, Vth_g + (size_t)row * L_SZ + c * 64 + ch * 8);
        }
    };

    issue_chunk(0, 0);
    CP_COMMIT();
    issue_chunk(1, 1);
    CP_COMMIT();

    uint32_t qoff[4];
#pragma unroll
    for (int ks = 0; ks < 4; ks++) {
        int r = wid * 16 + (lane & 15);
        int ch = ks * 2 + (lane >> 4);
        qoff[ks] = (uint32_t)(r * 128 + ((ch ^ (r & 7)) << 4));
    }
    uint32_t lbo[4][4];
#pragma unroll
    for (int np = 0; np < 4; np++) {
        int r = np * 16 + ((lane >> 4) << 3) + (lane & 7);
#pragma unroll
        for (int ks = 0; ks < 4; ks++) {
            int ch = ks * 2 + ((lane >> 3) & 1);
            lbo[np][ks] = (uint32_t)(r * 128 + ((ch ^ (r & 7)) << 4));
        }
    }

    uint32_t qfh[4][4];
    float oacc[8][4];
#pragma unroll
    for (int t = 0; t < 8; t++)
#pragma unroll
        for (int q = 0; q < 4; q++) oacc[t][q] = 0.f;
    float mrow[2] = {-INFINITY, -INFINITY};
    float lrow[2] = {0.f, 0.f};

#pragma unroll 1
    for (int c = 0; c < 16; c++) {
        const int st = c & 1;
        CP_WAIT1();
        __syncthreads();

        if (c == 0) {
#pragma unroll
            for (int ks = 0; ks < 4; ks++)
                ldsm4(qfh[ks], sb + A_OFF_QH + qoff[ks]);
        }

        const uint32_t kb = sb + A_OFF_KV + st * A_STAGE;
        const uint32_t vbh = kb + 8192;

        float sacc[8][4];
#pragma unroll
        for (int t = 0; t < 8; t++)
#pragma unroll
            for (int q = 0; q < 4; q++) sacc[t][q] = 0.f;
#pragma unroll
        for (int ks = 0; ks < 4; ks++) {
            uint32_t kth[4][4];
#pragma unroll
            for (int np = 0; np < 4; np++)
                ldsm4(kth[np], kb + lbo[np][ks]);
#pragma unroll
            for (int np = 0; np < 4; np++) {
                mma_f16(sacc[2*np],   qfh[ks], kth[np]);
                mma_f16(sacc[2*np+1], qfh[ks], kth[np] + 2);
            }
        }

#pragma unroll
        for (int r = 0; r < 2; r++) {
            float mx = mrow[r];
#pragma unroll
            for (int t = 0; t < 8; t++)
                mx = fmaxf(mx, fmaxf(sacc[t][2*r], sacc[t][2*r+1]));
            mx = fmaxf(mx, __shfl_xor_sync(0xffffffffu, mx, 1));
            mx = fmaxf(mx, __shfl_xor_sync(0xffffffffu, mx, 2));
            const float sc = exp2f(mrow[r] - mx);
            mrow[r] = mx;
            float sum = 0.f;
#pragma unroll
            for (int t = 0; t < 8; t++) {
                float p0 = exp2f(sacc[t][2*r]   - mx);
                float p1 = exp2f(sacc[t][2*r+1] - mx);
                sacc[t][2*r] = p0; sacc[t][2*r+1] = p1;
                sum += p0 + p1;
            }
            sum += __shfl_xor_sync(0xffffffffu, sum, 1);
            sum += __shfl_xor_sync(0xffffffffu, sum, 2);
            lrow[r] = lrow[r] * sc + sum;
#pragma unroll
            for (int t = 0; t < 8; t++) {
                oacc[t][2*r] *= sc; oacc[t][2*r+1] *= sc;
            }
        }

#pragma unroll
        for (int j = 0; j < 4; j++) {
            uint32_t pah[4];
            pah[0] = pack2h(sacc[2*j][0],   sacc[2*j][1]);
            pah[1] = pack2h(sacc[2*j][2],   sacc[2*j][3]);
            pah[2] = pack2h(sacc[2*j+1][0], sacc[2*j+1][1]);
            pah[3] = pack2h(sacc[2*j+1][2], sacc[2*j+1][3]);
            uint32_t vfh[4][4];
#pragma unroll
            for (int dp = 0; dp < 4; dp++)
                ldsm4(vfh[dp], vbh + lbo[dp][j]);
#pragma unroll
            for (int dp = 0; dp < 4; dp++) {
                mma_f16(oacc[2*dp],   pah, vfh[dp]);
                mma_f16(oacc[2*dp+1], pah, vfh[dp] + 2);
            }
        }

        __syncthreads();
        if (c + 2 < 16) issue_chunk(c + 2, st);
        CP_COMMIT();
    }

    const float inv0 = 1.f / lrow[0];
    const float inv1 = 1.f / lrow[1];
    const int q0 = qt * 128 + wid * 16 + (lane >> 2);
#pragma unroll
    for (int t = 0; t < 8; t++) {
        const int col = h * 64 + t * 8 + (lane & 3) * 2;
        const size_t o0 = ((size_t)(b * L_SZ + q0)) * DM + col;
        const size_t o1 = ((size_t)(b * L_SZ + q0 + 8)) * DM + col;
        *(uint32_t*)(Oh + o0) = pack2h(oacc[t][0] * inv0, oacc[t][1] * inv0);
        *(uint32_t*)(Oh + o1) = pack2h(oacc[t][2] * inv1, oacc[t][3] * inv1);
    }
}

// ============================================================================
// launch
// ============================================================================
extern "C" void kernel_launch(void* const* d_in, const int* in_sizes, int n_in,
                              void* d_out, int out_size)
{
    const float* x     = (const float*)d_in[0];
    const float* w_qkv = (const float*)d_in[1];
    const float* w_o   = (const float*)d_in[2];
    float* out = (float*)d_out;

    __half *xh_p, *wqh_p, *woh_p, *ah_p;
    __half *qh_p, *kh_p, *vth_p;
    cudaGetSymbolAddress((void**)&xh_p,  g_xh);
    cudaGetSymbolAddress((void**)&wqh_p, g_wqh);
    cudaGetSymbolAddress((void**)&woh_p, g_woh);
    cudaGetSymbolAddress((void**)&ah_p,  g_ah);
    cudaGetSymbolAddress((void**)&qh_p,  g_qh);
    cudaGetSymbolAddress((void**)&kh_p,  g_kh);
    cudaGetSymbolAddress((void**)&vth_p, g_vth);

    cudaFuncSetAttribute(gemm_qkv_fused_kernel,
                         cudaFuncAttributeMaxDynamicSharedMemorySize, PGEMM_SMEM);
    cudaFuncSetAttribute(gemm_f16_kernel,
                         cudaFuncAttributeMaxDynamicSharedMemorySize, PGEMM_SMEM);
    cudaFuncSetAttribute(attn_f16_kernel,
                         cudaFuncAttributeMaxDynamicSharedMemorySize, ATTN_SMEM);

    convert_hi_kernel<<<(MROWS * DM / 8 + 255) / 256, 256>>>(x, xh_p, MROWS * DM / 8);
    convert_hi_kernel<<<(QKV_E * DM / 8 + 255) / 256, 256>>>(w_qkv, wqh_p, QKV_E * DM / 8);
    convert_hi_kernel<<<(DM * DM / 8 + 255) / 256, 256>>>(w_o, woh_p, DM * DM / 8);

    // 1) QKV projection + fused norm/rope/transpose
    {
        dim3 grid(QKV_E / 128, MROWS / 128);
        gemm_qkv_fused_kernel<<<grid, 256, PGEMM_SMEM>>>(xh_p, wqh_p,
                                                         qh_p, kh_p, vth_p);
    }
    // 2) attention
    {
        dim3 grid(L_SZ / 128, NH, B_SZ);
        attn_f16_kernel<<<grid, 256, ATTN_SMEM>>>(qh_p, kh_p, vth_p, ah_p);
    }
    // 3) output projection
    {
        dim3 grid(DM / 128, MROWS / 128);
        gemm_f16_kernel<<<grid, 256, PGEMM_SMEM>>>(ah_p, woh_p, out, DM, DM);
    }
}